// round 2
// baseline (speedup 1.0000x reference)
#include <cuda_runtime.h>
#include <math.h>

#define NPTS 500000
#define DIM  64
#define NC   10000
#define TO   192            // 3*64 combined outputs (q|k|v)
#define BN_EPS 1e-5f

#define PS 68               // x_s row stride (floats), mult of 4
#define JS 196              // w_s row stride (floats), mult of 4

// ---------------- scratch (device globals: no allocation allowed) ------------
__device__ float    g_k[(size_t)NPTS * DIM];     // 128 MB
__device__ float    g_v[(size_t)NPTS * DIM];     // 128 MB
__device__ unsigned g_qmax[NC * DIM];            // order-encoded fp32 max
__device__ unsigned g_mmax[NC];
__device__ float    g_denom[NC];
__device__ float    g_inv[NC];
__device__ float    g_M[NPTS];
__device__ float    g_e[NPTS];
__device__ float    g_bnsum[DIM];
__device__ float    g_bnsq[DIM];
__device__ float    g_scale[DIM];
__device__ float    g_shift[DIM];

// Order-preserving fp32 <-> u32 mapping for integer atomicMax
__device__ __forceinline__ unsigned encf(float f) {
    unsigned u = __float_as_uint(f);
    return (u & 0x80000000u) ? ~u : (u | 0x80000000u);
}
__device__ __forceinline__ float decf(unsigned u) {
    return __uint_as_float((u & 0x80000000u) ? (u & 0x7FFFFFFFu) : ~u);
}
#define ENC_NEG_INF 0x007FFFFFu   // encf(-inf)

// ---------------- K0: init ---------------------------------------------------
__global__ void k_init() {
    int i = blockIdx.x * blockDim.x + threadIdx.x;
    if (i < NC * DIM) g_qmax[i] = ENC_NEG_INF;
    if (i < NC)       { g_mmax[i] = ENC_NEG_INF; g_denom[i] = 0.f; }
    if (i < DIM)      { g_bnsum[i] = 0.f; g_bnsq[i] = 0.f; }
}

// ---------------- K1: fused QKV GEMM + q segment-max + k/v store -------------
// Block: 128 threads, tile = 64 points x 192 outputs.
// Thread tile: 8 points x 12 outputs (96 accumulators).
__global__ __launch_bounds__(128, 3)
void k_qkv(const float* __restrict__ x, const int* __restrict__ cluster,
           const float* __restrict__ Wv, const float* __restrict__ bv,
           const float* __restrict__ Wk, const float* __restrict__ bk,
           const float* __restrict__ Wq, const float* __restrict__ bq) {
    extern __shared__ float sm[];
    float* w_s = sm;                    // [64][JS]  (transposed: w_s[d][j])
    float* x_s = sm + 64 * JS;          // [64][PS]  (x_s[p][d], reused as stage)
    float* b_s = x_s + 64 * PS;         // [192]
    __shared__ int c_s[64];

    const int tid = threadIdx.x;
    const int tx  = tid & 15;           // output-group 0..15
    const int ty  = tid >> 4;           // point-group 0..7
    const int j0  = tx * 12;
    const int p0  = ty * 8;

    // Load combined weights transposed + biases (once per block)
    for (int l = tid; l < TO * 16; l += 128) {
        int j = l >> 4, dc = l & 15;
        const float* Wsrc = (j < 64) ? Wq : (j < 128 ? Wk : Wv);
        int jr = j & 63;
        float4 wv = *(const float4*)&Wsrc[jr * 64 + dc * 4];
        w_s[(dc * 4 + 0) * JS + j] = wv.x;
        w_s[(dc * 4 + 1) * JS + j] = wv.y;
        w_s[(dc * 4 + 2) * JS + j] = wv.z;
        w_s[(dc * 4 + 3) * JS + j] = wv.w;
    }
    for (int l = tid; l < TO; l += 128)
        b_s[l] = (l < 64) ? bq[l] : (l < 128 ? bk[l - 64] : bv[l - 128]);
    __syncthreads();

    const int numTiles = (NPTS + 63) / 64;
    for (int tile = blockIdx.x; tile < numTiles; tile += gridDim.x) {
        const int base = tile * 64;

        // Load x tile [64 pts][64 dims], coalesced, into x_s[p][d]
        for (int l = tid; l < 64 * 16; l += 128) {
            int p = l >> 4, ch = l & 15;
            float4 xv = (base + p < NPTS)
                      ? *(const float4*)&x[(size_t)(base + p) * 64 + ch * 4]
                      : make_float4(0.f, 0.f, 0.f, 0.f);
            *(float4*)&x_s[p * PS + ch * 4] = xv;
        }
        if (tid < 64) c_s[tid] = (base + tid < NPTS) ? cluster[base + tid] : 0;
        __syncthreads();

        float acc[8][12];
        #pragma unroll
        for (int pp = 0; pp < 8; pp++)
            #pragma unroll
            for (int jj = 0; jj < 12; jj++) acc[pp][jj] = b_s[j0 + jj];

        #pragma unroll 4
        for (int d4 = 0; d4 < 16; d4++) {
            float xr[8][4];
            #pragma unroll
            for (int pp = 0; pp < 8; pp++) {
                float4 t = *(const float4*)&x_s[(p0 + pp) * PS + d4 * 4];
                xr[pp][0] = t.x; xr[pp][1] = t.y; xr[pp][2] = t.z; xr[pp][3] = t.w;
            }
            #pragma unroll
            for (int q = 0; q < 4; q++) {
                const int d = d4 * 4 + q;
                float4 w0 = *(const float4*)&w_s[d * JS + j0];
                float4 w1 = *(const float4*)&w_s[d * JS + j0 + 4];
                float4 w2 = *(const float4*)&w_s[d * JS + j0 + 8];
                float wr[12];
                wr[0] = w0.x; wr[1] = w0.y; wr[2]  = w0.z; wr[3]  = w0.w;
                wr[4] = w1.x; wr[5] = w1.y; wr[6]  = w1.z; wr[7]  = w1.w;
                wr[8] = w2.x; wr[9] = w2.y; wr[10] = w2.z; wr[11] = w2.w;
                #pragma unroll
                for (int pp = 0; pp < 8; pp++)
                    #pragma unroll
                    for (int jj = 0; jj < 12; jj++)
                        acc[pp][jj] = fmaf(xr[pp][q], wr[jj], acc[pp][jj]);
            }
        }
        __syncthreads();   // done reading x_s; safe to reuse as staging

        // q part: segment max via encoded integer atomicMax
        #pragma unroll
        for (int pp = 0; pp < 8; pp++) {
            const int p = p0 + pp;
            const bool valid = (base + p) < NPTS;
            const int cl = c_s[p];
            #pragma unroll
            for (int jj = 0; jj < 12; jj++) {
                const int gj = j0 + jj;
                if (gj < 64 && valid)
                    atomicMax(&g_qmax[cl * 64 + gj], encf(acc[pp][jj]));
            }
        }

        // k part: stage to shared, then coalesced float4 store
        #pragma unroll
        for (int pp = 0; pp < 8; pp++) {
            const int p = p0 + pp;
            #pragma unroll
            for (int jj = 0; jj < 12; jj++) {
                const int gj = j0 + jj;
                if (gj >= 64 && gj < 128) x_s[p * PS + (gj - 64)] = acc[pp][jj];
            }
        }
        __syncthreads();
        for (int l = tid; l < 64 * 16; l += 128) {
            int p = l >> 4, ch = l & 15;
            if (base + p < NPTS)
                *(float4*)&g_k[(size_t)(base + p) * 64 + ch * 4] =
                    *(float4*)&x_s[p * PS + ch * 4];
        }
        __syncthreads();

        // v part
        #pragma unroll
        for (int pp = 0; pp < 8; pp++) {
            const int p = p0 + pp;
            #pragma unroll
            for (int jj = 0; jj < 12; jj++) {
                const int gj = j0 + jj;
                if (gj >= 128) x_s[p * PS + (gj - 128)] = acc[pp][jj];
            }
        }
        __syncthreads();
        for (int l = tid; l < 64 * 16; l += 128) {
            int p = l >> 4, ch = l & 15;
            if (base + p < NPTS)
                *(float4*)&g_v[(size_t)(base + p) * 64 + ch * 4] =
                    *(float4*)&x_s[p * PS + ch * 4];
        }
        __syncthreads();
    }
}

// ---------------- K2: M[i] = q[cluster[i]] . k[i], segment max of M ----------
// 8 lanes per point, float4 loads, shfl reduce.
__global__ void k_score(const int* __restrict__ cluster) {
    int t = blockIdx.x * blockDim.x + threadIdx.x;
    int i = t >> 3;
    int r = t & 7;
    if (i >= NPTS) return;
    int cl = cluster[i];
    const float4* kp = (const float4*)&g_k[(size_t)i * 64];
    const uint4*  qp = (const uint4*)&g_qmax[cl * 64];
    float s = 0.f;
    #pragma unroll
    for (int h = 0; h < 2; h++) {
        float4 kv = kp[r + h * 8];
        uint4  qv = qp[r + h * 8];
        s += kv.x * decf(qv.x) + kv.y * decf(qv.y)
           + kv.z * decf(qv.z) + kv.w * decf(qv.w);
    }
    s += __shfl_down_sync(0xFFFFFFFFu, s, 4);
    s += __shfl_down_sync(0xFFFFFFFFu, s, 2);
    s += __shfl_down_sync(0xFFFFFFFFu, s, 1);
    if (r == 0) {
        g_M[i] = s;
        atomicMax(&g_mmax[cl], encf(s));
    }
}

// ---------------- K3: e = exp(M - mmax[c]); denom[c] += e --------------------
__global__ void k_expsum(const int* __restrict__ cluster) {
    int i = blockIdx.x * blockDim.x + threadIdx.x;
    if (i >= NPTS) return;
    int cl = cluster[i];
    float e = expf(g_M[i] - decf(g_mmax[cl]));
    g_e[i] = e;
    atomicAdd(&g_denom[cl], e);
}

// ---------------- K4: inv[c] = 1/denom[c] ------------------------------------
__global__ void k_invdenom() {
    int c = blockIdx.x * blockDim.x + threadIdx.x;
    if (c < NC) g_inv[c] = 1.0f / g_denom[c];
}

// ---------------- K5: BN statistics over h = attn * v ------------------------
// 256 thr: lane-column mapping so cluster/e/inv loads are warp-uniform.
__global__ void k_bnstats(const int* __restrict__ cluster) {
    const int tid = threadIdx.x;
    const int jj  = tid & 63;
    const int pg  = tid >> 6;            // 0..3
    float s = 0.f, s2 = 0.f;
    for (int i = blockIdx.x * 4 + pg; i < NPTS; i += gridDim.x * 4) {
        float attn = g_e[i] * g_inv[cluster[i]];
        float h = attn * g_v[(size_t)i * 64 + jj];
        s += h; s2 += h * h;
    }
    __shared__ float sh[64], sh2[64];
    if (tid < 64) { sh[tid] = 0.f; sh2[tid] = 0.f; }
    __syncthreads();
    atomicAdd(&sh[jj], s);
    atomicAdd(&sh2[jj], s2);
    __syncthreads();
    if (tid < 64) {
        atomicAdd(&g_bnsum[tid], sh[tid]);
        atomicAdd(&g_bnsq[tid],  sh2[tid]);
    }
}

// ---------------- K6: fold BN into per-column scale/shift --------------------
__global__ void k_bnscale(const float* __restrict__ gamma,
                          const float* __restrict__ beta) {
    int j = threadIdx.x;
    if (j >= DIM) return;
    float mean = g_bnsum[j] / (float)NPTS;
    float var  = g_bnsq[j] / (float)NPTS - mean * mean;
    float sc   = gamma[j] * rsqrtf(var + BN_EPS);
    g_scale[j] = sc;
    g_shift[j] = beta[j] - mean * sc;
}

// ---------------- K7: out = relu(h*scale + shift) ----------------------------
__global__ void k_out(const int* __restrict__ cluster, float* __restrict__ out) {
    int idx = blockIdx.x * blockDim.x + threadIdx.x;
    if (idx >= NPTS * 64) return;
    int i  = idx >> 6;
    int jj = idx & 63;
    float attn = g_e[i] * g_inv[cluster[i]];
    float h = attn * g_v[idx];
    float r = fmaf(h, g_scale[jj], g_shift[jj]);
    out[idx] = fmaxf(r, 0.f);
}

// ---------------- launcher ---------------------------------------------------
extern "C" void kernel_launch(void* const* d_in, const int* in_sizes, int n_in,
                              void* d_out, int out_size) {
    (void)in_sizes; (void)n_in; (void)out_size;
    const float* x       = (const float*)d_in[1];
    const int*   cluster = (const int*)  d_in[2];
    const float* Wv      = (const float*)d_in[3];
    const float* bv      = (const float*)d_in[4];
    const float* Wk      = (const float*)d_in[5];
    const float* bk      = (const float*)d_in[6];
    const float* Wq      = (const float*)d_in[7];
    const float* bq      = (const float*)d_in[8];
    const float* gamma   = (const float*)d_in[9];
    const float* beta    = (const float*)d_in[10];
    float* out = (float*)d_out;

    k_init<<<(NC * DIM + 255) / 256, 256>>>();

    size_t smem = (size_t)(64 * JS + 64 * PS + TO) * sizeof(float);
    cudaFuncSetAttribute(k_qkv, cudaFuncAttributeMaxDynamicSharedMemorySize,
                         (int)smem);
    k_qkv<<<888, 128, smem>>>(x, cluster, Wv, bv, Wk, bk, Wq, bq);

    k_score<<<(NPTS * 8 + 255) / 256, 256>>>(cluster);
    k_expsum<<<(NPTS + 255) / 256, 256>>>(cluster);
    k_invdenom<<<(NC + 255) / 256, 256>>>();
    k_bnstats<<<1184, 256>>>(cluster);
    k_bnscale<<<1, 64>>>(gamma, beta);
    k_out<<<(NPTS * 64 + 255) / 256, 256>>>(cluster, out);
}

// round 3
// speedup vs baseline: 1.1378x; 1.1378x over previous
#include <cuda_runtime.h>
#include <math.h>

#define NPTS 500000
#define DIM  64
#define NC   10000
#define TO   192            // 3*64 combined outputs (q|k|v)
#define BN_EPS 1e-5f

#define PS 68               // x_s row stride (floats), mult of 4
#define JS 196              // w_s row stride (floats), mult of 4

typedef unsigned long long ull;

// ---------------- scratch (device globals: no allocation allowed) ------------
__device__ float    g_k[(size_t)NPTS * DIM];     // 128 MB
__device__ float    g_v[(size_t)NPTS * DIM];     // 128 MB
__device__ unsigned g_qmax[NC * DIM];            // order-encoded fp32 max
__device__ unsigned g_mmax[NC];
__device__ float    g_denom[NC];
__device__ float    g_inv[NC];
__device__ float    g_M[NPTS];
__device__ float    g_e[NPTS];
__device__ float    g_bnsum[DIM];
__device__ float    g_bnsq[DIM];
__device__ float    g_scale[DIM];
__device__ float    g_shift[DIM];

// Order-preserving fp32 <-> u32 mapping for integer atomicMax
__device__ __forceinline__ unsigned encf(float f) {
    unsigned u = __float_as_uint(f);
    return (u & 0x80000000u) ? ~u : (u | 0x80000000u);
}
__device__ __forceinline__ float decf(unsigned u) {
    return __uint_as_float((u & 0x80000000u) ? (u & 0x7FFFFFFFu) : ~u);
}
#define ENC_NEG_INF 0x007FFFFFu   // encf(-inf)

// ---------------- packed fp32x2 helpers (sm_103a dual-FMA pipe) --------------
__device__ __forceinline__ ull pack_dup(float x) {
    ull r;
    asm("mov.b64 %0, {%1, %1};" : "=l"(r) : "f"(x));
    return r;
}
__device__ __forceinline__ void unpack2(ull p, float& lo, float& hi) {
    asm("mov.b64 {%0, %1}, %2;" : "=f"(lo), "=f"(hi) : "l"(p));
}
#define FMA_F32X2(d, a, b, c) \
    asm("fma.rn.f32x2 %0, %1, %2, %3;" : "=l"(d) : "l"(a), "l"(b), "l"(c))

// ---------------- K0: init ---------------------------------------------------
__global__ void k_init() {
    int i = blockIdx.x * blockDim.x + threadIdx.x;
    if (i < NC * DIM) g_qmax[i] = ENC_NEG_INF;
    if (i < NC)       { g_mmax[i] = ENC_NEG_INF; g_denom[i] = 0.f; }
    if (i < DIM)      { g_bnsum[i] = 0.f; g_bnsq[i] = 0.f; }
}

// ---------------- K1: fused QKV GEMM (f32x2) + q segment-max + k/v store -----
// Block: 128 threads, tile = 64 points x 192 outputs.
// Thread tile: 8 points x 12 outputs = 8 x 6 packed f32x2 accumulators.
__global__ __launch_bounds__(128, 3)
void k_qkv(const float* __restrict__ x, const int* __restrict__ cluster,
           const float* __restrict__ Wv, const float* __restrict__ bv,
           const float* __restrict__ Wk, const float* __restrict__ bk,
           const float* __restrict__ Wq, const float* __restrict__ bq) {
    extern __shared__ float sm[];
    float* w_s = sm;                    // [64][JS]  (transposed: w_s[d][j])
    float* x_s = sm + 64 * JS;          // [64][PS]  (x_s[p][d], reused as stage)
    float* b_s = x_s + 64 * PS;         // [192]
    __shared__ int c_s[64];

    const int tid = threadIdx.x;
    const int tx  = tid & 15;           // output-group 0..15
    const int ty  = tid >> 4;           // point-group 0..7
    const int j0  = tx * 12;            // even -> u64-aligned pairs
    const int p0  = ty * 8;

    // Load combined weights transposed + biases (once per block)
    for (int l = tid; l < TO * 16; l += 128) {
        int j = l >> 4, dc = l & 15;
        const float* Wsrc = (j < 64) ? Wq : (j < 128 ? Wk : Wv);
        int jr = j & 63;
        float4 wv = *(const float4*)&Wsrc[jr * 64 + dc * 4];
        w_s[(dc * 4 + 0) * JS + j] = wv.x;
        w_s[(dc * 4 + 1) * JS + j] = wv.y;
        w_s[(dc * 4 + 2) * JS + j] = wv.z;
        w_s[(dc * 4 + 3) * JS + j] = wv.w;
    }
    for (int l = tid; l < TO; l += 128)
        b_s[l] = (l < 64) ? bq[l] : (l < 128 ? bk[l - 64] : bv[l - 128]);
    __syncthreads();

    const int numTiles = (NPTS + 63) / 64;
    for (int tile = blockIdx.x; tile < numTiles; tile += gridDim.x) {
        const int base = tile * 64;

        // Load x tile [64 pts][64 dims], coalesced, into x_s[p][d]
        for (int l = tid; l < 64 * 16; l += 128) {
            int p = l >> 4, ch = l & 15;
            float4 xv = (base + p < NPTS)
                      ? *(const float4*)&x[(size_t)(base + p) * 64 + ch * 4]
                      : make_float4(0.f, 0.f, 0.f, 0.f);
            *(float4*)&x_s[p * PS + ch * 4] = xv;
        }
        if (tid < 64) c_s[tid] = (base + tid < NPTS) ? cluster[base + tid] : 0;
        __syncthreads();

        // packed accumulators: acc[pp][m] holds outputs (j0+2m, j0+2m+1)
        ull acc[8][6];
        {
            const ull* bp = (const ull*)&b_s[j0];
            #pragma unroll
            for (int m = 0; m < 6; m++) {
                ull bb = bp[m];
                #pragma unroll
                for (int pp = 0; pp < 8; pp++) acc[pp][m] = bb;
            }
        }

        #pragma unroll 4
        for (int d4 = 0; d4 < 16; d4++) {
            float xr[8][4];
            #pragma unroll
            for (int pp = 0; pp < 8; pp++) {
                float4 t = *(const float4*)&x_s[(p0 + pp) * PS + d4 * 4];
                xr[pp][0] = t.x; xr[pp][1] = t.y; xr[pp][2] = t.z; xr[pp][3] = t.w;
            }
            #pragma unroll
            for (int q = 0; q < 4; q++) {
                const int d = d4 * 4 + q;
                const ull* wp = (const ull*)&w_s[d * JS + j0];
                ull wr[6];
                #pragma unroll
                for (int m = 0; m < 6; m++) wr[m] = wp[m];
                #pragma unroll
                for (int pp = 0; pp < 8; pp++) {
                    ull a = pack_dup(xr[pp][q]);
                    #pragma unroll
                    for (int m = 0; m < 6; m++)
                        FMA_F32X2(acc[pp][m], a, wr[m], acc[pp][m]);
                }
            }
        }
        __syncthreads();   // done reading x_s; safe to reuse as staging

        // q part: segment max via encoded integer atomicMax
        #pragma unroll
        for (int pp = 0; pp < 8; pp++) {
            const int p = p0 + pp;
            const bool valid = (base + p) < NPTS;
            const int cl = c_s[p];
            #pragma unroll
            for (int m = 0; m < 6; m++) {
                float lo, hi;
                unpack2(acc[pp][m], lo, hi);
                const int gj = j0 + 2 * m;
                if (gj < 64 && valid) {
                    atomicMax(&g_qmax[cl * 64 + gj],     encf(lo));
                    atomicMax(&g_qmax[cl * 64 + gj + 1], encf(hi));
                }
            }
        }

        // k part: stage to shared, then coalesced float4 store
        #pragma unroll
        for (int pp = 0; pp < 8; pp++) {
            const int p = p0 + pp;
            #pragma unroll
            for (int m = 0; m < 6; m++) {
                const int gj = j0 + 2 * m;
                if (gj >= 64 && gj < 128) {
                    float lo, hi;
                    unpack2(acc[pp][m], lo, hi);
                    x_s[p * PS + (gj - 64)]     = lo;
                    x_s[p * PS + (gj - 64) + 1] = hi;
                }
            }
        }
        __syncthreads();
        for (int l = tid; l < 64 * 16; l += 128) {
            int p = l >> 4, ch = l & 15;
            if (base + p < NPTS)
                *(float4*)&g_k[(size_t)(base + p) * 64 + ch * 4] =
                    *(float4*)&x_s[p * PS + ch * 4];
        }
        __syncthreads();

        // v part
        #pragma unroll
        for (int pp = 0; pp < 8; pp++) {
            const int p = p0 + pp;
            #pragma unroll
            for (int m = 0; m < 6; m++) {
                const int gj = j0 + 2 * m;
                if (gj >= 128) {
                    float lo, hi;
                    unpack2(acc[pp][m], lo, hi);
                    x_s[p * PS + (gj - 128)]     = lo;
                    x_s[p * PS + (gj - 128) + 1] = hi;
                }
            }
        }
        __syncthreads();
        for (int l = tid; l < 64 * 16; l += 128) {
            int p = l >> 4, ch = l & 15;
            if (base + p < NPTS)
                *(float4*)&g_v[(size_t)(base + p) * 64 + ch * 4] =
                    *(float4*)&x_s[p * PS + ch * 4];
        }
        __syncthreads();
    }
}

// ---------------- K2: M[i] = q[cluster[i]] . k[i], segment max of M ----------
// 8 lanes per point, float4 loads, shfl reduce.
__global__ void k_score(const int* __restrict__ cluster) {
    int t = blockIdx.x * blockDim.x + threadIdx.x;
    int i = t >> 3;
    int r = t & 7;
    if (i >= NPTS) return;
    int cl = cluster[i];
    const float4* kp = (const float4*)&g_k[(size_t)i * 64];
    const uint4*  qp = (const uint4*)&g_qmax[cl * 64];
    float s = 0.f;
    #pragma unroll
    for (int h = 0; h < 2; h++) {
        float4 kv = kp[r + h * 8];
        uint4  qv = qp[r + h * 8];
        s += kv.x * decf(qv.x) + kv.y * decf(qv.y)
           + kv.z * decf(qv.z) + kv.w * decf(qv.w);
    }
    s += __shfl_down_sync(0xFFFFFFFFu, s, 4);
    s += __shfl_down_sync(0xFFFFFFFFu, s, 2);
    s += __shfl_down_sync(0xFFFFFFFFu, s, 1);
    if (r == 0) {
        g_M[i] = s;
        atomicMax(&g_mmax[cl], encf(s));
    }
}

// ---------------- K3: e = exp(M - mmax[c]); denom[c] += e --------------------
__global__ void k_expsum(const int* __restrict__ cluster) {
    int i = blockIdx.x * blockDim.x + threadIdx.x;
    if (i >= NPTS) return;
    int cl = cluster[i];
    float e = expf(g_M[i] - decf(g_mmax[cl]));
    g_e[i] = e;
    atomicAdd(&g_denom[cl], e);
}

// ---------------- K4: inv[c] = 1/denom[c] ------------------------------------
__global__ void k_invdenom() {
    int c = blockIdx.x * blockDim.x + threadIdx.x;
    if (c < NC) g_inv[c] = 1.0f / g_denom[c];
}

// ---------------- K5: BN statistics over h = attn * v ------------------------
// 256 thr: lane-column mapping so cluster/e/inv loads are warp-uniform.
__global__ void k_bnstats(const int* __restrict__ cluster) {
    const int tid = threadIdx.x;
    const int jj  = tid & 63;
    const int pg  = tid >> 6;            // 0..3
    float s = 0.f, s2 = 0.f;
    for (int i = blockIdx.x * 4 + pg; i < NPTS; i += gridDim.x * 4) {
        float attn = g_e[i] * g_inv[cluster[i]];
        float h = attn * g_v[(size_t)i * 64 + jj];
        s += h; s2 += h * h;
    }
    __shared__ float sh[64], sh2[64];
    if (tid < 64) { sh[tid] = 0.f; sh2[tid] = 0.f; }
    __syncthreads();
    atomicAdd(&sh[jj], s);
    atomicAdd(&sh2[jj], s2);
    __syncthreads();
    if (tid < 64) {
        atomicAdd(&g_bnsum[tid], sh[tid]);
        atomicAdd(&g_bnsq[tid],  sh2[tid]);
    }
}

// ---------------- K6: fold BN into per-column scale/shift --------------------
__global__ void k_bnscale(const float* __restrict__ gamma,
                          const float* __restrict__ beta) {
    int j = threadIdx.x;
    if (j >= DIM) return;
    float mean = g_bnsum[j] / (float)NPTS;
    float var  = g_bnsq[j] / (float)NPTS - mean * mean;
    float sc   = gamma[j] * rsqrtf(var + BN_EPS);
    g_scale[j] = sc;
    g_shift[j] = beta[j] - mean * sc;
}

// ---------------- K7: out = relu(h*scale + shift) ----------------------------
__global__ void k_out(const int* __restrict__ cluster, float* __restrict__ out) {
    int idx = blockIdx.x * blockDim.x + threadIdx.x;
    if (idx >= NPTS * 64) return;
    int i  = idx >> 6;
    int jj = idx & 63;
    float attn = g_e[i] * g_inv[cluster[i]];
    float h = attn * g_v[idx];
    float r = fmaf(h, g_scale[jj], g_shift[jj]);
    out[idx] = fmaxf(r, 0.f);
}

// ---------------- launcher ---------------------------------------------------
extern "C" void kernel_launch(void* const* d_in, const int* in_sizes, int n_in,
                              void* d_out, int out_size) {
    (void)in_sizes; (void)n_in; (void)out_size;
    const float* x       = (const float*)d_in[1];
    const int*   cluster = (const int*)  d_in[2];
    const float* Wv      = (const float*)d_in[3];
    const float* bv      = (const float*)d_in[4];
    const float* Wk      = (const float*)d_in[5];
    const float* bk      = (const float*)d_in[6];
    const float* Wq      = (const float*)d_in[7];
    const float* bq      = (const float*)d_in[8];
    const float* gamma   = (const float*)d_in[9];
    const float* beta    = (const float*)d_in[10];
    float* out = (float*)d_out;

    k_init<<<(NC * DIM + 255) / 256, 256>>>();

    size_t smem = (size_t)(64 * JS + 64 * PS + TO) * sizeof(float);
    cudaFuncSetAttribute(k_qkv, cudaFuncAttributeMaxDynamicSharedMemorySize,
                         (int)smem);
    k_qkv<<<888, 128, smem>>>(x, cluster, Wv, bv, Wk, bk, Wq, bq);

    k_score<<<(NPTS * 8 + 255) / 256, 256>>>(cluster);
    k_expsum<<<(NPTS + 255) / 256, 256>>>(cluster);
    k_invdenom<<<(NC + 255) / 256, 256>>>();
    k_bnstats<<<1184, 256>>>(cluster);
    k_bnscale<<<1, 64>>>(gamma, beta);
    k_out<<<(NPTS * 64 + 255) / 256, 256>>>(cluster, out);
}

// round 6
// speedup vs baseline: 1.2718x; 1.1178x over previous
#include <cuda_runtime.h>
#include <math.h>

#define NPTS 500000
#define DIM  64
#define NC   10000
#define TO   128            // 2*64 combined outputs (q|v)  — k eliminated
#define BN_EPS 1e-5f

#define PS 68               // x_s row stride (floats), mult of 4
#define JS 132              // w_s row stride (floats), mult of 4

typedef unsigned long long ull;

// ---------------- scratch (device globals: no allocation allowed) ------------
__device__ float    g_v[(size_t)NPTS * DIM];     // 128 MB
__device__ unsigned g_qmax[NC * DIM];            // order-encoded fp32 max
__device__ float    g_qw[NC * DIM];              // Wk^T q[c]
__device__ float    g_qb[NC];                    // q[c] . bk
__device__ unsigned g_mmax[NC];
__device__ float    g_denom[NC];
__device__ float    g_inv[NC];
__device__ float    g_M[NPTS];
__device__ float    g_e[NPTS];
__device__ float    g_bnsum[DIM];
__device__ float    g_bnsq[DIM];
__device__ float    g_scale[DIM];
__device__ float    g_shift[DIM];

// Order-preserving fp32 <-> u32 mapping for integer atomicMax
__device__ __forceinline__ unsigned encf(float f) {
    unsigned u = __float_as_uint(f);
    return (u & 0x80000000u) ? ~u : (u | 0x80000000u);
}
__device__ __forceinline__ float decf(unsigned u) {
    return __uint_as_float((u & 0x80000000u) ? (u & 0x7FFFFFFFu) : ~u);
}
#define ENC_NEG_INF 0x007FFFFFu   // encf(-inf)

// ---------------- packed fp32x2 helpers (sm_103a dual-FMA pipe) --------------
__device__ __forceinline__ ull pack_dup(float x) {
    ull r;
    asm("mov.b64 %0, {%1, %1};" : "=l"(r) : "f"(x));
    return r;
}
__device__ __forceinline__ void unpack2(ull p, float& lo, float& hi) {
    asm("mov.b64 {%0, %1}, %2;" : "=f"(lo), "=f"(hi) : "l"(p));
}
#define FMA_F32X2(d, a, b, c) \
    asm("fma.rn.f32x2 %0, %1, %2, %3;" : "=l"(d) : "l"(a), "l"(b), "l"(c))

// ---------------- K0: init ---------------------------------------------------
__global__ void k_init() {
    int i = blockIdx.x * blockDim.x + threadIdx.x;
    if (i < NC * DIM) g_qmax[i] = ENC_NEG_INF;
    if (i < NC)       { g_mmax[i] = ENC_NEG_INF; g_denom[i] = 0.f; }
    if (i < DIM)      { g_bnsum[i] = 0.f; g_bnsq[i] = 0.f; }
}

// ---------------- K1: fused QV GEMM (f32x2) + q segment-max + v store --------
// Block: 128 threads, tile = 64 points x 128 outputs.
// Thread tile: 8 points x 8 outputs = 8 x 4 packed f32x2 accumulators.
__global__ __launch_bounds__(128, 3)
void k_qv(const float* __restrict__ x, const int* __restrict__ cluster,
          const float* __restrict__ Wv, const float* __restrict__ bv,
          const float* __restrict__ Wq, const float* __restrict__ bq) {
    extern __shared__ float sm[];
    float* w_s = sm;                    // [64][JS]  (transposed: w_s[d][j])
    float* x_s = sm + 64 * JS;          // [64][PS]  (x_s[p][d], reused as stage)
    float* b_s = x_s + 64 * PS;         // [128]
    __shared__ int c_s[64];

    const int tid = threadIdx.x;
    const int tx  = tid & 15;           // output-group 0..15
    const int ty  = tid >> 4;           // point-group 0..7
    const int j0  = tx * 8;             // even -> u64-aligned pairs
    const int p0  = ty * 8;

    // Load combined weights transposed + biases (once per block)
    for (int l = tid; l < TO * 16; l += 128) {
        int j = l >> 4, dc = l & 15;
        const float* Wsrc = (j < 64) ? Wq : Wv;
        int jr = j & 63;
        float4 wv = *(const float4*)&Wsrc[jr * 64 + dc * 4];
        w_s[(dc * 4 + 0) * JS + j] = wv.x;
        w_s[(dc * 4 + 1) * JS + j] = wv.y;
        w_s[(dc * 4 + 2) * JS + j] = wv.z;
        w_s[(dc * 4 + 3) * JS + j] = wv.w;
    }
    for (int l = tid; l < TO; l += 128)
        b_s[l] = (l < 64) ? bq[l] : bv[l - 64];
    __syncthreads();

    const int numTiles = (NPTS + 63) / 64;
    for (int tile = blockIdx.x; tile < numTiles; tile += gridDim.x) {
        const int base = tile * 64;

        // Load x tile [64 pts][64 dims], coalesced, into x_s[p][d]
        for (int l = tid; l < 64 * 16; l += 128) {
            int p = l >> 4, ch = l & 15;
            float4 xv = (base + p < NPTS)
                      ? *(const float4*)&x[(size_t)(base + p) * 64 + ch * 4]
                      : make_float4(0.f, 0.f, 0.f, 0.f);
            *(float4*)&x_s[p * PS + ch * 4] = xv;
        }
        if (tid < 64) c_s[tid] = (base + tid < NPTS) ? cluster[base + tid] : 0;
        __syncthreads();

        // packed accumulators: acc[pp][m] holds outputs (j0+2m, j0+2m+1)
        ull acc[8][4];
        {
            const ull* bp = (const ull*)&b_s[j0];
            #pragma unroll
            for (int m = 0; m < 4; m++) {
                ull bb = bp[m];
                #pragma unroll
                for (int pp = 0; pp < 8; pp++) acc[pp][m] = bb;
            }
        }

        #pragma unroll 4
        for (int d4 = 0; d4 < 16; d4++) {
            float xr[8][4];
            #pragma unroll
            for (int pp = 0; pp < 8; pp++) {
                float4 t = *(const float4*)&x_s[(p0 + pp) * PS + d4 * 4];
                xr[pp][0] = t.x; xr[pp][1] = t.y; xr[pp][2] = t.z; xr[pp][3] = t.w;
            }
            #pragma unroll
            for (int q = 0; q < 4; q++) {
                const int d = d4 * 4 + q;
                const ull* wp = (const ull*)&w_s[d * JS + j0];
                ull wr[4];
                #pragma unroll
                for (int m = 0; m < 4; m++) wr[m] = wp[m];
                #pragma unroll
                for (int pp = 0; pp < 8; pp++) {
                    ull a = pack_dup(xr[pp][q]);
                    #pragma unroll
                    for (int m = 0; m < 4; m++)
                        FMA_F32X2(acc[pp][m], a, wr[m], acc[pp][m]);
                }
            }
        }

        // q part (tx < 8): segment max via encoded integer atomicMax
        if (tx < 8) {
            #pragma unroll
            for (int pp = 0; pp < 8; pp++) {
                const int p = p0 + pp;
                if (base + p < NPTS) {
                    const int cl = c_s[p];
                    #pragma unroll
                    for (int m = 0; m < 4; m++) {
                        float lo, hi;
                        unpack2(acc[pp][m], lo, hi);
                        atomicMax(&g_qmax[cl * 64 + j0 + 2 * m],     encf(lo));
                        atomicMax(&g_qmax[cl * 64 + j0 + 2 * m + 1], encf(hi));
                    }
                }
            }
        }
        __syncthreads();   // all reads of x_s done; reuse as v staging

        // v part (tx >= 8): stage packed pairs directly (8B aligned)
        if (tx >= 8) {
            #pragma unroll
            for (int pp = 0; pp < 8; pp++) {
                const int p = p0 + pp;
                #pragma unroll
                for (int m = 0; m < 4; m++)
                    *(ull*)&x_s[p * PS + (j0 - 64) + 2 * m] = acc[pp][m];
            }
        }
        __syncthreads();
        for (int l = tid; l < 64 * 16; l += 128) {
            int p = l >> 4, ch = l & 15;
            if (base + p < NPTS)
                *(float4*)&g_v[(size_t)(base + p) * 64 + ch * 4] =
                    *(float4*)&x_s[p * PS + ch * 4];
        }
        __syncthreads();
    }
}

// ---------------- K2: per-cluster transform qw[c] = Wk^T q[c], qb = q.bk -----
// 256 threads = 4 clusters x 64 dims.
__global__ __launch_bounds__(256)
void k_qtrans(const float* __restrict__ Wk, const float* __restrict__ bk) {
    __shared__ float wks[64 * 64];
    __shared__ float qs[4][64];
    __shared__ float bks[64];
    const int tid = threadIdx.x;
    for (int l = tid; l < 64 * 64; l += 256) wks[l] = Wk[l];
    if (tid < 64) bks[tid] = bk[tid];
    const int cl = tid >> 6;            // 0..3
    const int d  = tid & 63;
    const int c  = blockIdx.x * 4 + cl;
    qs[cl][d] = decf(g_qmax[c * 64 + d]);
    __syncthreads();
    float s = 0.f;
    #pragma unroll 8
    for (int j = 0; j < 64; j++)
        s = fmaf(qs[cl][j], wks[j * 64 + d], s);
    g_qw[c * 64 + d] = s;
    if (d == 0) {
        float t = 0.f;
        #pragma unroll 8
        for (int j = 0; j < 64; j++) t = fmaf(qs[cl][j], bks[j], t);
        g_qb[c] = t;
    }
}

// ---------------- K3: M[i] = qw[cluster[i]] . x[i] + qb, segment max ---------
// 8 lanes per point, float4 loads, shfl reduce.
__global__ void k_score(const float* __restrict__ x,
                        const int* __restrict__ cluster) {
    int t = blockIdx.x * blockDim.x + threadIdx.x;
    int i = t >> 3;
    int r = t & 7;
    if (i >= NPTS) return;
    int cl = cluster[i];
    const float4* xp = (const float4*)&x[(size_t)i * 64];
    const float4* qp = (const float4*)&g_qw[cl * 64];
    float s = 0.f;
    #pragma unroll
    for (int h = 0; h < 2; h++) {
        float4 xv = xp[r + h * 8];
        float4 qv = qp[r + h * 8];
        s += xv.x * qv.x + xv.y * qv.y + xv.z * qv.z + xv.w * qv.w;
    }
    s += __shfl_down_sync(0xFFFFFFFFu, s, 4);
    s += __shfl_down_sync(0xFFFFFFFFu, s, 2);
    s += __shfl_down_sync(0xFFFFFFFFu, s, 1);
    if (r == 0) {
        s += g_qb[cl];
        g_M[i] = s;
        atomicMax(&g_mmax[cl], encf(s));
    }
}

// ---------------- K4: e = exp(M - mmax[c]); denom[c] += e --------------------
__global__ void k_expsum(const int* __restrict__ cluster) {
    int i = blockIdx.x * blockDim.x + threadIdx.x;
    if (i >= NPTS) return;
    int cl = cluster[i];
    float e = expf(g_M[i] - decf(g_mmax[cl]));
    g_e[i] = e;
    atomicAdd(&g_denom[cl], e);
}

// ---------------- K5: inv[c] = 1/denom[c] ------------------------------------
__global__ void k_invdenom() {
    int c = blockIdx.x * blockDim.x + threadIdx.x;
    if (c < NC) g_inv[c] = 1.0f / g_denom[c];
}

// ---------------- K6: BN statistics over h = attn * v ------------------------
__global__ void k_bnstats(const int* __restrict__ cluster) {
    const int tid = threadIdx.x;
    const int jj  = tid & 63;
    const int pg  = tid >> 6;            // 0..3
    float s = 0.f, s2 = 0.f;
    for (int i = blockIdx.x * 4 + pg; i < NPTS; i += gridDim.x * 4) {
        float attn = g_e[i] * g_inv[cluster[i]];
        float h = attn * g_v[(size_t)i * 64 + jj];
        s += h; s2 += h * h;
    }
    __shared__ float sh[64], sh2[64];
    if (tid < 64) { sh[tid] = 0.f; sh2[tid] = 0.f; }
    __syncthreads();
    atomicAdd(&sh[jj], s);
    atomicAdd(&sh2[jj], s2);
    __syncthreads();
    if (tid < 64) {
        atomicAdd(&g_bnsum[tid], sh[tid]);
        atomicAdd(&g_bnsq[tid],  sh2[tid]);
    }
}

// ---------------- K7: fold BN into per-column scale/shift --------------------
__global__ void k_bnscale(const float* __restrict__ gamma,
                          const float* __restrict__ beta) {
    int j = threadIdx.x;
    if (j >= DIM) return;
    float mean = g_bnsum[j] / (float)NPTS;
    float var  = g_bnsq[j] / (float)NPTS - mean * mean;
    float sc   = gamma[j] * rsqrtf(var + BN_EPS);
    g_scale[j] = sc;
    g_shift[j] = beta[j] - mean * sc;
}

// ---------------- K8: out = relu(h*scale + shift) ----------------------------
__global__ void k_out(const int* __restrict__ cluster, float* __restrict__ out) {
    int idx = blockIdx.x * blockDim.x + threadIdx.x;
    if (idx >= NPTS * 64) return;
    int i  = idx >> 6;
    int jj = idx & 63;
    float attn = g_e[i] * g_inv[cluster[i]];
    float h = attn * g_v[idx];
    float r = fmaf(h, g_scale[jj], g_shift[jj]);
    out[idx] = fmaxf(r, 0.f);
}

// ---------------- launcher ---------------------------------------------------
extern "C" void kernel_launch(void* const* d_in, const int* in_sizes, int n_in,
                              void* d_out, int out_size) {
    (void)in_sizes; (void)n_in; (void)out_size;
    const float* x       = (const float*)d_in[1];
    const int*   cluster = (const int*)  d_in[2];
    const float* Wv      = (const float*)d_in[3];
    const float* bv      = (const float*)d_in[4];
    const float* Wk      = (const float*)d_in[5];
    const float* bk      = (const float*)d_in[6];
    const float* Wq      = (const float*)d_in[7];
    const float* bq      = (const float*)d_in[8];
    const float* gamma   = (const float*)d_in[9];
    const float* beta    = (const float*)d_in[10];
    float* out = (float*)d_out;

    k_init<<<(NC * DIM + 255) / 256, 256>>>();

    size_t smem = (size_t)(64 * JS + 64 * PS + TO) * sizeof(float);
    cudaFuncSetAttribute(k_qv, cudaFuncAttributeMaxDynamicSharedMemorySize,
                         (int)smem);
    k_qv<<<888, 128, smem>>>(x, cluster, Wv, bv, Wq, bq);

    k_qtrans<<<NC / 4, 256>>>(Wk, bk);
    k_score<<<(NPTS * 8 + 255) / 256, 256>>>(x, cluster);
    k_expsum<<<(NPTS + 255) / 256, 256>>>(cluster);
    k_invdenom<<<(NC + 255) / 256, 256>>>();
    k_bnstats<<<1184, 256>>>(cluster);
    k_bnscale<<<1, 64>>>(gamma, beta);
    k_out<<<(NPTS * 64 + 255) / 256, 256>>>(cluster, out);
}